// round 1
// baseline (speedup 1.0000x reference)
#include <cuda_runtime.h>
#include <cuda_bf16.h>
#include <math.h>

// Problem constants
#define BB   4
#define TT   2048
#define CC   1024
#define NQ   8
#define DD   128
#define MM   (BB*TT)          // 8192 rows
#define NQKV (DD*(NQ+2))      // 1280

// ---------------- scratch (no allocations allowed) ----------------
__device__ float g_Wcat[CC * NQKV];     // [1024,1280]  packed K|V|Q0..Q7 weights
__device__ float g_qkv [MM * NQKV];     // [8192,1280]  k|v|q per token
__device__ float g_attn[MM * CC];       // [8192,1024]  attention output (B,T,NQ,D)

// ---------------- weight pack ----------------
__global__ void pack_w_kernel(const float* __restrict__ Wk,
                              const float* __restrict__ Wv,
                              const float* __restrict__ Wq,
                              float* __restrict__ Wcat) {
    int idx = blockIdx.x * 256 + threadIdx.x;
    if (idx >= CC * NQKV) return;
    int c = idx / NQKV;
    int n = idx % NQKV;
    float v;
    if (n < DD)            v = Wk[c * DD + n];
    else if (n < 2 * DD)   v = Wv[c * DD + (n - DD)];
    else {
        int h = (n - 2 * DD) >> 7;
        int d = (n - 2 * DD) & 127;
        v = Wq[(h * CC + c) * DD + d];
    }
    Wcat[idx] = v;
}

// ---------------- fp32 SGEMM: C = A[M,K] @ B[K,N] (+bias) ----------------
// BM=128, BN=128, BK=16, 256 threads, 8x8 per thread (64-split tiles).
// Requires M%128==0, N%128==0, K%16==0 (true for all uses here).
#define GBM 128
#define GBN 128
#define GBK 16

__global__ __launch_bounds__(256, 2)
void sgemm_kernel(const float* __restrict__ A, const float* __restrict__ B,
                  float* __restrict__ C, const float* __restrict__ bias,
                  int M, int N, int K) {
    __shared__ float As[GBK][GBM];   // transposed A tile
    __shared__ float Bs[GBK][GBN];

    const int tid = threadIdx.x;
    const int tx = tid & 15;     // n dir
    const int ty = tid >> 4;     // m dir
    const int m0 = blockIdx.y * GBM;
    const int n0 = blockIdx.x * GBN;

    const float* Aptr = A + (size_t)m0 * K;
    const float* Bptr = B + n0;

    float acc[8][8];
#pragma unroll
    for (int i = 0; i < 8; i++)
#pragma unroll
        for (int j = 0; j < 8; j++) acc[i][j] = 0.f;

    const int a_row  = tid >> 2;   // 0..63 (two passes -> 128 rows)
    const int a_colv = tid & 3;    // float4 index within 16 cols
    const int b_row  = tid >> 5;   // 0..7 (two passes -> 16 rows)
    const int b_colv = tid & 31;   // float4 index within 128 cols

    for (int k0 = 0; k0 < K; k0 += GBK) {
#pragma unroll
        for (int p = 0; p < 2; p++) {
            int r = a_row + p * 64;
            float4 v = *reinterpret_cast<const float4*>(Aptr + (size_t)r * K + k0 + a_colv * 4);
            As[a_colv * 4 + 0][r] = v.x;
            As[a_colv * 4 + 1][r] = v.y;
            As[a_colv * 4 + 2][r] = v.z;
            As[a_colv * 4 + 3][r] = v.w;
        }
#pragma unroll
        for (int p = 0; p < 2; p++) {
            int r = b_row + p * 8;
            *reinterpret_cast<float4*>(&Bs[r][b_colv * 4]) =
                *reinterpret_cast<const float4*>(Bptr + (size_t)(k0 + r) * N + b_colv * 4);
        }
        __syncthreads();

#pragma unroll
        for (int kk = 0; kk < GBK; kk++) {
            float4 a0 = *reinterpret_cast<const float4*>(&As[kk][ty * 4]);
            float4 a1 = *reinterpret_cast<const float4*>(&As[kk][64 + ty * 4]);
            float4 b0 = *reinterpret_cast<const float4*>(&Bs[kk][tx * 4]);
            float4 b1 = *reinterpret_cast<const float4*>(&Bs[kk][64 + tx * 4]);
            float a[8] = {a0.x, a0.y, a0.z, a0.w, a1.x, a1.y, a1.z, a1.w};
            float b[8] = {b0.x, b0.y, b0.z, b0.w, b1.x, b1.y, b1.z, b1.w};
#pragma unroll
            for (int i = 0; i < 8; i++)
#pragma unroll
                for (int j = 0; j < 8; j++)
                    acc[i][j] += a[i] * b[j];
        }
        __syncthreads();
    }

#pragma unroll
    for (int i = 0; i < 8; i++) {
        int m = m0 + ((i < 4) ? (ty * 4 + i) : (64 + ty * 4 + (i - 4)));
#pragma unroll
        for (int jj = 0; jj < 2; jj++) {
            int n = n0 + jj * 64 + tx * 4;
            float4 v;
            v.x = acc[i][jj * 4 + 0];
            v.y = acc[i][jj * 4 + 1];
            v.z = acc[i][jj * 4 + 2];
            v.w = acc[i][jj * 4 + 3];
            if (bias) {
                v.x += bias[n]; v.y += bias[n + 1]; v.z += bias[n + 2]; v.w += bias[n + 3];
            }
            *reinterpret_cast<float4*>(C + (size_t)m * N + n) = v;
        }
    }
}

// ---------------- causal MQA flash attention ----------------
// 64 query rows x 64 key cols per iter, D=128, 256 threads (16x16),
// each thread: 4x4 S micro-tile, 4x8 O micro-tile.
#define QPITCH 132
#define VPITCH 132
#define PPITCH 68
#define ASMEM  ((64*QPITCH + 128*64 + 64*VPITCH + 64*PPITCH) * 4)

__global__ __launch_bounds__(256, 1)
void mqa_kernel(const float* __restrict__ qkv, float* __restrict__ out) {
    extern __shared__ float sm[];
    float* Qs = sm;                       // [64][QPITCH]
    float* Kt = Qs + 64 * QPITCH;         // [128][64] transposed + swizzled
    float* Vs = Kt + 128 * 64;            // [64][VPITCH]
    float* Ps = Vs + 64 * VPITCH;         // [64][PPITCH]

    const int tid = threadIdx.x;
    const int tx = tid & 15;
    const int ty = tid >> 4;
    const int qt = gridDim.x - 1 - blockIdx.x;   // heavy tiles first
    const int h  = blockIdx.y;
    const int b  = blockIdx.z;
    const int q0 = qt * 64;
    const float scale = 1.0f / 32.0f;            // C^-0.5

    const float* kbase = qkv + (size_t)(b * TT) * NQKV;          // k at +0
    const float* vbase = kbase + DD;                              // v at +128
    const float* qbase = kbase + 2 * DD + h * DD;                 // q_h

    // Load Q tile (pre-scaled)
    for (int l = tid; l < 64 * 32; l += 256) {
        int r  = l >> 5;
        int dv = l & 31;
        float4 v = *reinterpret_cast<const float4*>(qbase + (size_t)(q0 + r) * NQKV + dv * 4);
        v.x *= scale; v.y *= scale; v.z *= scale; v.w *= scale;
        *reinterpret_cast<float4*>(&Qs[r * QPITCH + dv * 4]) = v;
    }

    float o[4][8];
#pragma unroll
    for (int i = 0; i < 4; i++)
#pragma unroll
        for (int j = 0; j < 8; j++) o[i][j] = 0.f;
    float mrow[4], lrow[4];
#pragma unroll
    for (int i = 0; i < 4; i++) { mrow[i] = -1e30f; lrow[i] = 0.f; }

    const int nkb = qt + 1;
    for (int kb = 0; kb < nkb; kb++) {
        const int s0 = kb * 64;
        __syncthreads();   // protect Kt/Vs/Ps from previous iteration (and publish Qs on iter 0)

        // K tile: transpose + XOR swizzle (groups of 4 keys swizzled by (d>>2)&15)
        for (int l = tid; l < 64 * 32; l += 256) {
            int s  = l >> 5;
            int dv = l & 31;
            float4 v = *reinterpret_cast<const float4*>(kbase + (size_t)(s0 + s) * NQKV + dv * 4);
            int sc = s ^ ((dv & 15) << 2);
            Kt[(dv * 4 + 0) * 64 + sc] = v.x;
            Kt[(dv * 4 + 1) * 64 + sc] = v.y;
            Kt[(dv * 4 + 2) * 64 + sc] = v.z;
            Kt[(dv * 4 + 3) * 64 + sc] = v.w;
        }
        // V tile (natural layout)
        for (int l = tid; l < 64 * 32; l += 256) {
            int s  = l >> 5;
            int dv = l & 31;
            float4 v = *reinterpret_cast<const float4*>(vbase + (size_t)(s0 + s) * NQKV + dv * 4);
            *reinterpret_cast<float4*>(&Vs[s * VPITCH + dv * 4]) = v;
        }
        __syncthreads();

        // S = Q @ K^T  (4x4 per thread)
        float sacc[4][4];
#pragma unroll
        for (int i = 0; i < 4; i++)
#pragma unroll
            for (int j = 0; j < 4; j++) sacc[i][j] = 0.f;

#pragma unroll 8
        for (int d = 0; d < 128; d++) {
            float a0 = Qs[(ty * 4 + 0) * QPITCH + d];
            float a1 = Qs[(ty * 4 + 1) * QPITCH + d];
            float a2 = Qs[(ty * 4 + 2) * QPITCH + d];
            float a3 = Qs[(ty * 4 + 3) * QPITCH + d];
            int swz = ((d >> 2) & 15) << 2;
            float4 bv = *reinterpret_cast<const float4*>(&Kt[d * 64 + ((tx * 4) ^ swz)]);
            sacc[0][0] += a0 * bv.x; sacc[0][1] += a0 * bv.y; sacc[0][2] += a0 * bv.z; sacc[0][3] += a0 * bv.w;
            sacc[1][0] += a1 * bv.x; sacc[1][1] += a1 * bv.y; sacc[1][2] += a1 * bv.z; sacc[1][3] += a1 * bv.w;
            sacc[2][0] += a2 * bv.x; sacc[2][1] += a2 * bv.y; sacc[2][2] += a2 * bv.z; sacc[2][3] += a2 * bv.w;
            sacc[3][0] += a3 * bv.x; sacc[3][1] += a3 * bv.y; sacc[3][2] += a3 * bv.z; sacc[3][3] += a3 * bv.w;
        }

        // Causal mask (only the diagonal block needs it)
        if (kb == nkb - 1) {
#pragma unroll
            for (int i = 0; i < 4; i++)
#pragma unroll
                for (int j = 0; j < 4; j++)
                    if (tx * 4 + j > ty * 4 + i) sacc[i][j] = -1e30f;
        }

        // Online softmax (row reduction across the 16-lane half-warp)
#pragma unroll
        for (int i = 0; i < 4; i++) {
            float mloc = fmaxf(fmaxf(sacc[i][0], sacc[i][1]), fmaxf(sacc[i][2], sacc[i][3]));
#pragma unroll
            for (int off = 8; off >= 1; off >>= 1)
                mloc = fmaxf(mloc, __shfl_xor_sync(0xffffffffu, mloc, off));
            float mnew = fmaxf(mrow[i], mloc);
            float corr = __expf(mrow[i] - mnew);
            mrow[i] = mnew;
            float lloc = 0.f;
#pragma unroll
            for (int j = 0; j < 4; j++) {
                float p = __expf(sacc[i][j] - mnew);
                sacc[i][j] = p;
                lloc += p;
            }
#pragma unroll
            for (int off = 8; off >= 1; off >>= 1)
                lloc += __shfl_xor_sync(0xffffffffu, lloc, off);
            lrow[i] = lrow[i] * corr + lloc;
#pragma unroll
            for (int j = 0; j < 8; j++) o[i][j] *= corr;
        }

        // Stage P to smem
#pragma unroll
        for (int i = 0; i < 4; i++) {
            float4 p4;
            p4.x = sacc[i][0]; p4.y = sacc[i][1]; p4.z = sacc[i][2]; p4.w = sacc[i][3];
            *reinterpret_cast<float4*>(&Ps[(ty * 4 + i) * PPITCH + tx * 4]) = p4;
        }
        __syncthreads();

        // O += P @ V
#pragma unroll 4
        for (int s = 0; s < 64; s++) {
            float p0 = Ps[(ty * 4 + 0) * PPITCH + s];
            float p1 = Ps[(ty * 4 + 1) * PPITCH + s];
            float p2 = Ps[(ty * 4 + 2) * PPITCH + s];
            float p3 = Ps[(ty * 4 + 3) * PPITCH + s];
            float4 v0 = *reinterpret_cast<const float4*>(&Vs[s * VPITCH + tx * 4]);
            float4 v1 = *reinterpret_cast<const float4*>(&Vs[s * VPITCH + 64 + tx * 4]);
            o[0][0] += p0 * v0.x; o[0][1] += p0 * v0.y; o[0][2] += p0 * v0.z; o[0][3] += p0 * v0.w;
            o[0][4] += p0 * v1.x; o[0][5] += p0 * v1.y; o[0][6] += p0 * v1.z; o[0][7] += p0 * v1.w;
            o[1][0] += p1 * v0.x; o[1][1] += p1 * v0.y; o[1][2] += p1 * v0.z; o[1][3] += p1 * v0.w;
            o[1][4] += p1 * v1.x; o[1][5] += p1 * v1.y; o[1][6] += p1 * v1.z; o[1][7] += p1 * v1.w;
            o[2][0] += p2 * v0.x; o[2][1] += p2 * v0.y; o[2][2] += p2 * v0.z; o[2][3] += p2 * v0.w;
            o[2][4] += p2 * v1.x; o[2][5] += p2 * v1.y; o[2][6] += p2 * v1.z; o[2][7] += p2 * v1.w;
            o[3][0] += p3 * v0.x; o[3][1] += p3 * v0.y; o[3][2] += p3 * v0.z; o[3][3] += p3 * v0.w;
            o[3][4] += p3 * v1.x; o[3][5] += p3 * v1.y; o[3][6] += p3 * v1.z; o[3][7] += p3 * v1.w;
        }
    }

    // Epilogue: normalize and write [B,T,NQ,D]
#pragma unroll
    for (int i = 0; i < 4; i++) {
        float rl = 1.0f / lrow[i];
        int qg = q0 + ty * 4 + i;
        float* op = out + ((size_t)(b * TT + qg) * NQ + h) * DD;
        float4 w0, w1;
        w0.x = o[i][0] * rl; w0.y = o[i][1] * rl; w0.z = o[i][2] * rl; w0.w = o[i][3] * rl;
        w1.x = o[i][4] * rl; w1.y = o[i][5] * rl; w1.z = o[i][6] * rl; w1.w = o[i][7] * rl;
        *reinterpret_cast<float4*>(op + tx * 4)      = w0;
        *reinterpret_cast<float4*>(op + 64 + tx * 4) = w1;
    }
}

// ---------------- launch ----------------
extern "C" void kernel_launch(void* const* d_in, const int* in_sizes, int n_in,
                              void* d_out, int out_size) {
    const float* x  = (const float*)d_in[0];
    const float* Wk = (const float*)d_in[1];
    const float* Wv = (const float*)d_in[2];
    const float* Wq = (const float*)d_in[3];
    const float* Wp = (const float*)d_in[4];
    const float* bp = (const float*)d_in[5];
    float* out = (float*)d_out;

    float *wcat, *qkv, *attn;
    cudaGetSymbolAddress((void**)&wcat, g_Wcat);
    cudaGetSymbolAddress((void**)&qkv,  g_qkv);
    cudaGetSymbolAddress((void**)&attn, g_attn);

    cudaFuncSetAttribute(mqa_kernel, cudaFuncAttributeMaxDynamicSharedMemorySize, ASMEM);

    // 1) pack weights into one [C, 1280] matrix
    pack_w_kernel<<<(CC * NQKV + 255) / 256, 256>>>(Wk, Wv, Wq, wcat);

    // 2) fused QKV projection: [8192,1024] @ [1024,1280]
    sgemm_kernel<<<dim3(NQKV / GBN, MM / GBM), 256>>>(x, wcat, qkv, nullptr, MM, NQKV, CC);

    // 3) causal MQA attention -> [B,T,NQ,D]
    mqa_kernel<<<dim3(TT / 64, NQ, BB), 256, ASMEM>>>(qkv, attn);

    // 4) output projection with bias: [8192,1024] @ [1024,1024] + bp
    sgemm_kernel<<<dim3(CC / GBN, MM / GBM), 256>>>(attn, Wp, out, bp, MM, CC, CC);
}

// round 3
// speedup vs baseline: 1.1522x; 1.1522x over previous
#include <cuda_runtime.h>
#include <cuda_bf16.h>
#include <mma.h>
#include <cstdint>
#include <math.h>

using namespace nvcuda;

// Problem constants
#define BB   4
#define TT   2048
#define CC   1024
#define NQ   8
#define DD   128
#define MM   (BB*TT)          // 8192 rows
#define NQKV (DD*(NQ+2))      // 1280

// ---------------- scratch (no allocations allowed) ----------------
__device__ float g_Wcat[NQKV * CC];     // [1280][1024] K-major (transposed, tf32-rounded)
__device__ float g_WpT [CC * CC];       // [1024][1024] K-major (transposed, tf32-rounded)
__device__ float g_qkv [MM * NQKV];     // [8192][1280]  k|v|q per token
__device__ float g_attn[MM * CC];       // [8192][1024]  attention output (B,T,NQ,D)

__device__ __forceinline__ float to_tf32(float x) {
    float r;
    asm("cvt.rna.tf32.f32 %0, %1;" : "=f"(r) : "f"(x));
    return r;
}

// ---------------- weight transposes (to K-major [N][K], tf32-rounded) ----------------
__global__ void pack_qkv_t_kernel(const float* __restrict__ Wk,
                                  const float* __restrict__ Wv,
                                  const float* __restrict__ Wq,
                                  float* __restrict__ out) {
    __shared__ float t[32][33];
    int c0 = blockIdx.x * 32;
    int n0 = blockIdx.y * 32;
    int tx = threadIdx.x, ty = threadIdx.y;
#pragma unroll
    for (int p = 0; p < 4; p++) {
        int c = c0 + ty + p * 8;
        int n = n0 + tx;
        float v;
        if (n < DD)            v = Wk[c * DD + n];
        else if (n < 2 * DD)   v = Wv[c * DD + (n - DD)];
        else {
            int h = (n - 2 * DD) >> 7;
            int d = (n - 2 * DD) & 127;
            v = Wq[((size_t)h * CC + c) * DD + d];
        }
        t[ty + p * 8][tx] = to_tf32(v);
    }
    __syncthreads();
#pragma unroll
    for (int p = 0; p < 4; p++)
        out[(size_t)(n0 + ty + p * 8) * CC + c0 + tx] = t[tx][ty + p * 8];
}

__global__ void pack_wp_t_kernel(const float* __restrict__ Wp, float* __restrict__ out) {
    __shared__ float t[32][33];
    int c0 = blockIdx.x * 32;
    int n0 = blockIdx.y * 32;
    int tx = threadIdx.x, ty = threadIdx.y;
#pragma unroll
    for (int p = 0; p < 4; p++)
        t[ty + p * 8][tx] = to_tf32(Wp[(size_t)(c0 + ty + p * 8) * CC + n0 + tx]);
    __syncthreads();
#pragma unroll
    for (int p = 0; p < 4; p++)
        out[(size_t)(n0 + ty + p * 8) * CC + c0 + tx] = t[tx][ty + p * 8];
}

// ---------------- wmma tf32 GEMM: C[M,N] = A[M,K] @ Bt[N,K]^T (+bias) ----------------
// CTA tile 128x128, BK=16, 8 warps (4x2), warp tile 32x64 = 2x4 m16n16k8 frags.
// A rounded to tf32 on smem store; Bt pre-rounded by pack kernels.
#define GPAD 20   // smem row pitch (floats), multiple of 4 for wmma ldm

__global__ __launch_bounds__(256, 2)
void wmma_gemm(const float* __restrict__ A, const float* __restrict__ Bt,
               const float* __restrict__ bias, float* __restrict__ C,
               int M, int N, int K) {
    __shared__ float As[2][128][GPAD];
    __shared__ float Bs[2][128][GPAD];

    const int tid  = threadIdx.x;
    const int warp = tid >> 5;
    const int lane = tid & 31;
    const int wm   = warp >> 1;       // 0..3
    const int wn   = warp & 1;        // 0..1
    const int m0 = blockIdx.y * 128;
    const int n0 = blockIdx.x * 128;

    const float* Ab = A  + (size_t)m0 * K;
    const float* Bb = Bt + (size_t)n0 * K;

    wmma::fragment<wmma::accumulator, 16, 16, 8, float> acc[2][4];
#pragma unroll
    for (int i = 0; i < 2; i++)
#pragma unroll
        for (int j = 0; j < 4; j++)
            wmma::fill_fragment(acc[i][j], 0.0f);

    const int lr = tid >> 1;          // 0..127
    const int lc = (tid & 1) * 8;     // 0 or 8

    const int nk = K / 16;

    // load chunk 0
    {
        const float* ap = Ab + (size_t)lr * K + lc;
        const float* bp = Bb + (size_t)lr * K + lc;
        float4 a0 = *reinterpret_cast<const float4*>(ap);
        float4 a1 = *reinterpret_cast<const float4*>(ap + 4);
        float4 b0 = *reinterpret_cast<const float4*>(bp);
        float4 b1 = *reinterpret_cast<const float4*>(bp + 4);
        a0.x=to_tf32(a0.x); a0.y=to_tf32(a0.y); a0.z=to_tf32(a0.z); a0.w=to_tf32(a0.w);
        a1.x=to_tf32(a1.x); a1.y=to_tf32(a1.y); a1.z=to_tf32(a1.z); a1.w=to_tf32(a1.w);
        *reinterpret_cast<float4*>(&As[0][lr][lc])     = a0;
        *reinterpret_cast<float4*>(&As[0][lr][lc + 4]) = a1;
        *reinterpret_cast<float4*>(&Bs[0][lr][lc])     = b0;
        *reinterpret_cast<float4*>(&Bs[0][lr][lc + 4]) = b1;
    }
    __syncthreads();

    int buf = 0;
    for (int c = 0; c < nk; c++) {
        float4 ra0, ra1, rb0, rb1;
        const bool pf = (c + 1 < nk);
        if (pf) {
            const float* ap = Ab + (size_t)lr * K + (c + 1) * 16 + lc;
            const float* bp = Bb + (size_t)lr * K + (c + 1) * 16 + lc;
            ra0 = *reinterpret_cast<const float4*>(ap);
            ra1 = *reinterpret_cast<const float4*>(ap + 4);
            rb0 = *reinterpret_cast<const float4*>(bp);
            rb1 = *reinterpret_cast<const float4*>(bp + 4);
        }

#pragma unroll
        for (int ks = 0; ks < 2; ks++) {
            wmma::fragment<wmma::matrix_a, 16, 16, 8, wmma::precision::tf32, wmma::row_major> af[2];
            wmma::fragment<wmma::matrix_b, 16, 16, 8, wmma::precision::tf32, wmma::col_major> bf[4];
#pragma unroll
            for (int i = 0; i < 2; i++)
                wmma::load_matrix_sync(af[i], &As[buf][wm * 32 + i * 16][ks * 8], GPAD);
#pragma unroll
            for (int j = 0; j < 4; j++)
                wmma::load_matrix_sync(bf[j], &Bs[buf][wn * 64 + j * 16][ks * 8], GPAD);
#pragma unroll
            for (int i = 0; i < 2; i++)
#pragma unroll
                for (int j = 0; j < 4; j++)
                    wmma::mma_sync(acc[i][j], af[i], bf[j], acc[i][j]);
        }

        if (pf) {
            int nb = buf ^ 1;
            ra0.x=to_tf32(ra0.x); ra0.y=to_tf32(ra0.y); ra0.z=to_tf32(ra0.z); ra0.w=to_tf32(ra0.w);
            ra1.x=to_tf32(ra1.x); ra1.y=to_tf32(ra1.y); ra1.z=to_tf32(ra1.z); ra1.w=to_tf32(ra1.w);
            *reinterpret_cast<float4*>(&As[nb][lr][lc])     = ra0;
            *reinterpret_cast<float4*>(&As[nb][lr][lc + 4]) = ra1;
            *reinterpret_cast<float4*>(&Bs[nb][lr][lc])     = rb0;
            *reinterpret_cast<float4*>(&Bs[nb][lr][lc + 4]) = rb1;
        }
        __syncthreads();
        buf ^= 1;
    }

    // epilogue via per-warp smem stage (reuse As) for coalesced + bias stores
    float* stage = &As[0][0][0] + warp * 320;   // 16 rows x GPAD pitch
    const int er = lane >> 1;
    const int ec = (lane & 1) * 8;
#pragma unroll
    for (int i = 0; i < 2; i++) {
#pragma unroll
        for (int j = 0; j < 4; j++) {
            wmma::store_matrix_sync(stage, acc[i][j], GPAD, wmma::mem_row_major);
            __syncwarp();
            int gm = m0 + wm * 32 + i * 16 + er;
            int gn = n0 + wn * 64 + j * 16 + ec;
            float4 v0 = *reinterpret_cast<const float4*>(stage + er * GPAD + ec);
            float4 v1 = *reinterpret_cast<const float4*>(stage + er * GPAD + ec + 4);
            if (bias) {
                v0.x += bias[gn];     v0.y += bias[gn + 1];
                v0.z += bias[gn + 2]; v0.w += bias[gn + 3];
                v1.x += bias[gn + 4]; v1.y += bias[gn + 5];
                v1.z += bias[gn + 6]; v1.w += bias[gn + 7];
            }
            *reinterpret_cast<float4*>(C + (size_t)gm * N + gn)     = v0;
            *reinterpret_cast<float4*>(C + (size_t)gm * N + gn + 4) = v1;
            __syncwarp();
        }
    }
}

// ---------------- causal MQA flash attention (fp32, known-good) ----------------
#define QPITCH 132
#define VPITCH 132
#define PPITCH 68
#define ASMEM  ((64*QPITCH + 128*64 + 64*VPITCH + 64*PPITCH) * 4)

__global__ __launch_bounds__(256, 1)
void mqa_kernel(const float* __restrict__ qkv, float* __restrict__ out) {
    extern __shared__ float smf[];
    float* Qs = smf;
    float* Kt = Qs + 64 * QPITCH;
    float* Vs = Kt + 128 * 64;
    float* Ps = Vs + 64 * VPITCH;

    const int tid = threadIdx.x;
    const int tx = tid & 15;
    const int ty = tid >> 4;
    const int qt = gridDim.x - 1 - blockIdx.x;
    const int h  = blockIdx.y;
    const int b  = blockIdx.z;
    const int q0 = qt * 64;
    const float scale = 1.0f / 32.0f;

    const float* kbase = qkv + (size_t)(b * TT) * NQKV;
    const float* vbase = kbase + DD;
    const float* qbase = kbase + 2 * DD + h * DD;

    for (int l = tid; l < 64 * 32; l += 256) {
        int r  = l >> 5;
        int dv = l & 31;
        float4 v = *reinterpret_cast<const float4*>(qbase + (size_t)(q0 + r) * NQKV + dv * 4);
        v.x *= scale; v.y *= scale; v.z *= scale; v.w *= scale;
        *reinterpret_cast<float4*>(&Qs[r * QPITCH + dv * 4]) = v;
    }

    float o[4][8];
#pragma unroll
    for (int i = 0; i < 4; i++)
#pragma unroll
        for (int j = 0; j < 8; j++) o[i][j] = 0.f;
    float mrow[4], lrow[4];
#pragma unroll
    for (int i = 0; i < 4; i++) { mrow[i] = -1e30f; lrow[i] = 0.f; }

    const int nkb = qt + 1;
    for (int kb = 0; kb < nkb; kb++) {
        const int s0 = kb * 64;
        __syncthreads();

        for (int l = tid; l < 64 * 32; l += 256) {
            int s  = l >> 5;
            int dv = l & 31;
            float4 v = *reinterpret_cast<const float4*>(kbase + (size_t)(s0 + s) * NQKV + dv * 4);
            int sc = s ^ ((dv & 15) << 2);
            Kt[(dv * 4 + 0) * 64 + sc] = v.x;
            Kt[(dv * 4 + 1) * 64 + sc] = v.y;
            Kt[(dv * 4 + 2) * 64 + sc] = v.z;
            Kt[(dv * 4 + 3) * 64 + sc] = v.w;
        }
        for (int l = tid; l < 64 * 32; l += 256) {
            int s  = l >> 5;
            int dv = l & 31;
            float4 v = *reinterpret_cast<const float4*>(vbase + (size_t)(s0 + s) * NQKV + dv * 4);
            *reinterpret_cast<float4*>(&Vs[s * VPITCH + dv * 4]) = v;
        }
        __syncthreads();

        float sacc[4][4];
#pragma unroll
        for (int i = 0; i < 4; i++)
#pragma unroll
            for (int j = 0; j < 4; j++) sacc[i][j] = 0.f;

#pragma unroll 8
        for (int d = 0; d < 128; d++) {
            float a0 = Qs[(ty * 4 + 0) * QPITCH + d];
            float a1 = Qs[(ty * 4 + 1) * QPITCH + d];
            float a2 = Qs[(ty * 4 + 2) * QPITCH + d];
            float a3 = Qs[(ty * 4 + 3) * QPITCH + d];
            int swz = ((d >> 2) & 15) << 2;
            float4 bv = *reinterpret_cast<const float4*>(&Kt[d * 64 + ((tx * 4) ^ swz)]);
            sacc[0][0] += a0 * bv.x; sacc[0][1] += a0 * bv.y; sacc[0][2] += a0 * bv.z; sacc[0][3] += a0 * bv.w;
            sacc[1][0] += a1 * bv.x; sacc[1][1] += a1 * bv.y; sacc[1][2] += a1 * bv.z; sacc[1][3] += a1 * bv.w;
            sacc[2][0] += a2 * bv.x; sacc[2][1] += a2 * bv.y; sacc[2][2] += a2 * bv.z; sacc[2][3] += a2 * bv.w;
            sacc[3][0] += a3 * bv.x; sacc[3][1] += a3 * bv.y; sacc[3][2] += a3 * bv.z; sacc[3][3] += a3 * bv.w;
        }

        if (kb == nkb - 1) {
#pragma unroll
            for (int i = 0; i < 4; i++)
#pragma unroll
                for (int j = 0; j < 4; j++)
                    if (tx * 4 + j > ty * 4 + i) sacc[i][j] = -1e30f;
        }

#pragma unroll
        for (int i = 0; i < 4; i++) {
            float mloc = fmaxf(fmaxf(sacc[i][0], sacc[i][1]), fmaxf(sacc[i][2], sacc[i][3]));
#pragma unroll
            for (int off = 8; off >= 1; off >>= 1)
                mloc = fmaxf(mloc, __shfl_xor_sync(0xffffffffu, mloc, off));
            float mnew = fmaxf(mrow[i], mloc);
            float corr = __expf(mrow[i] - mnew);
            mrow[i] = mnew;
            float lloc = 0.f;
#pragma unroll
            for (int j = 0; j < 4; j++) {
                float p = __expf(sacc[i][j] - mnew);
                sacc[i][j] = p;
                lloc += p;
            }
#pragma unroll
            for (int off = 8; off >= 1; off >>= 1)
                lloc += __shfl_xor_sync(0xffffffffu, lloc, off);
            lrow[i] = lrow[i] * corr + lloc;
#pragma unroll
            for (int j = 0; j < 8; j++) o[i][j] *= corr;
        }

#pragma unroll
        for (int i = 0; i < 4; i++) {
            float4 p4;
            p4.x = sacc[i][0]; p4.y = sacc[i][1]; p4.z = sacc[i][2]; p4.w = sacc[i][3];
            *reinterpret_cast<float4*>(&Ps[(ty * 4 + i) * PPITCH + tx * 4]) = p4;
        }
        __syncthreads();

#pragma unroll 4
        for (int s = 0; s < 64; s++) {
            float p0 = Ps[(ty * 4 + 0) * PPITCH + s];
            float p1 = Ps[(ty * 4 + 1) * PPITCH + s];
            float p2 = Ps[(ty * 4 + 2) * PPITCH + s];
            float p3 = Ps[(ty * 4 + 3) * PPITCH + s];
            float4 v0 = *reinterpret_cast<const float4*>(&Vs[s * VPITCH + tx * 4]);
            float4 v1 = *reinterpret_cast<const float4*>(&Vs[s * VPITCH + 64 + tx * 4]);
            o[0][0] += p0 * v0.x; o[0][1] += p0 * v0.y; o[0][2] += p0 * v0.z; o[0][3] += p0 * v0.w;
            o[0][4] += p0 * v1.x; o[0][5] += p0 * v1.y; o[0][6] += p0 * v1.z; o[0][7] += p0 * v1.w;
            o[1][0] += p1 * v0.x; o[1][1] += p1 * v0.y; o[1][2] += p1 * v0.z; o[1][3] += p1 * v0.w;
            o[1][4] += p1 * v1.x; o[1][5] += p1 * v1.y; o[1][6] += p1 * v1.z; o[1][7] += p1 * v1.w;
            o[2][0] += p2 * v0.x; o[2][1] += p2 * v0.y; o[2][2] += p2 * v0.z; o[2][3] += p2 * v0.w;
            o[2][4] += p2 * v1.x; o[2][5] += p2 * v1.y; o[2][6] += p2 * v1.z; o[2][7] += p2 * v1.w;
            o[3][0] += p3 * v0.x; o[3][1] += p3 * v0.y; o[3][2] += p3 * v0.z; o[3][3] += p3 * v0.w;
            o[3][4] += p3 * v1.x; o[3][5] += p3 * v1.y; o[3][6] += p3 * v1.z; o[3][7] += p3 * v1.w;
        }
    }

#pragma unroll
    for (int i = 0; i < 4; i++) {
        float rl = 1.0f / lrow[i];
        int qg = q0 + ty * 4 + i;
        float* op = out + ((size_t)(b * TT + qg) * NQ + h) * DD;
        float4 w0, w1;
        w0.x = o[i][0] * rl; w0.y = o[i][1] * rl; w0.z = o[i][2] * rl; w0.w = o[i][3] * rl;
        w1.x = o[i][4] * rl; w1.y = o[i][5] * rl; w1.z = o[i][6] * rl; w1.w = o[i][7] * rl;
        *reinterpret_cast<float4*>(op + tx * 4)      = w0;
        *reinterpret_cast<float4*>(op + 64 + tx * 4) = w1;
    }
}

// ---------------- launch ----------------
extern "C" void kernel_launch(void* const* d_in, const int* in_sizes, int n_in,
                              void* d_out, int out_size) {
    const float* x  = (const float*)d_in[0];
    const float* Wk = (const float*)d_in[1];
    const float* Wv = (const float*)d_in[2];
    const float* Wq = (const float*)d_in[3];
    const float* Wp = (const float*)d_in[4];
    const float* bp = (const float*)d_in[5];
    float* out = (float*)d_out;

    float *wcat, *wpT, *qkv, *attn;
    cudaGetSymbolAddress((void**)&wcat, g_Wcat);
    cudaGetSymbolAddress((void**)&wpT,  g_WpT);
    cudaGetSymbolAddress((void**)&qkv,  g_qkv);
    cudaGetSymbolAddress((void**)&attn, g_attn);

    cudaFuncSetAttribute(mqa_kernel, cudaFuncAttributeMaxDynamicSharedMemorySize, ASMEM);

    // 1) transpose+pack weights to K-major (tf32-rounded)
    pack_qkv_t_kernel<<<dim3(CC / 32, NQKV / 32), dim3(32, 8)>>>(Wk, Wv, Wq, wcat);
    pack_wp_t_kernel<<<dim3(CC / 32, CC / 32), dim3(32, 8)>>>(Wp, wpT);

    // 2) fused QKV projection (wmma tf32): [8192,1024] @ [1024,1280]
    wmma_gemm<<<dim3(NQKV / 128, MM / 128), 256>>>(x, wcat, nullptr, qkv, MM, NQKV, CC);

    // 3) causal MQA attention -> [B,T,NQ,D]
    mqa_kernel<<<dim3(TT / 64, NQ, BB), 256, ASMEM>>>(qkv, attn);

    // 4) output projection (wmma tf32) + bias
    wmma_gemm<<<dim3(CC / 128, MM / 128), 256>>>(attn, wpT, bp, out, MM, CC, CC);
}